// round 1
// baseline (speedup 1.0000x reference)
#include <cuda_runtime.h>
#include <math.h>

#define LEVELS 16
#define MAXRES 2048

struct LP { float resm1[LEVELS]; float fres[LEVELS]; };

// Replicates reference fp32: int32((c / res) * 2047) with round-nearest div/mul,
// truncation toward zero (all values non-negative).
__device__ __forceinline__ int quantize(float c, float fres) {
    return (int)__fmul_rn(__fdiv_rn(c, fres), 2047.0f);
}

__global__ void __launch_bounds__(256) triplane_kernel(
    const float* __restrict__ positions,
    const float* __restrict__ table,
    float* __restrict__ out, int B, LP lp)
{
    int b = blockIdx.x * blockDim.x + threadIdx.x;
    if (b >= B) return;
    float px = positions[3*b+0];
    float py = positions[3*b+1];
    float pz = positions[3*b+2];

    const float2* t0 = (const float2*)table;          // plane 0: (x,y)
    const float2* t1 = t0 + MAXRES*MAXRES;            // plane 1: (y,z)
    const float2* t2 = t1 + MAXRES*MAXRES;            // plane 2: (z,x)

    float r[2*LEVELS];

#pragma unroll
    for (int l = 0; l < LEVELS; l++) {
        float resm1 = lp.resm1[l];
        float fres  = lp.fres[l];

        // pos = p*(res-1) + 0.5, NO fma contraction (match reference mul-then-add)
        float posx = __fadd_rn(__fmul_rn(px, resm1), 0.5f);
        float posy = __fadd_rn(__fmul_rn(py, resm1), 0.5f);
        float posz = __fadd_rn(__fmul_rn(pz, resm1), 0.5f);
        float gx = floorf(posx), gy = floorf(posy), gz = floorf(posz);
        float fx = posx - gx, fy = posy - gy, fz = posz - gz;

        // per-axis coarse-grid quantization, reused across the 3 planes
        int cxm = quantize(gx, fres), cxp = quantize(gx + 1.0f, fres);
        int cym = quantize(gy, fres), cyp = quantize(gy + 1.0f, fres);
        int czm = quantize(gz, fres), czp = quantize(gz + 1.0f, fres);

        // issue all 12 gathers up front for MLP
        float2 a00 = __ldg(&t0[cxm + cym*MAXRES]);
        float2 a10 = __ldg(&t0[cxp + cym*MAXRES]);
        float2 a01 = __ldg(&t0[cxm + cyp*MAXRES]);
        float2 a11 = __ldg(&t0[cxp + cyp*MAXRES]);

        float2 b00 = __ldg(&t1[cym + czm*MAXRES]);
        float2 b10 = __ldg(&t1[cyp + czm*MAXRES]);
        float2 b01 = __ldg(&t1[cym + czp*MAXRES]);
        float2 b11 = __ldg(&t1[cyp + czp*MAXRES]);

        float2 c00 = __ldg(&t2[czm + cxm*MAXRES]);
        float2 c10 = __ldg(&t2[czp + cxm*MAXRES]);
        float2 c01 = __ldg(&t2[czm + cxp*MAXRES]);
        float2 c11 = __ldg(&t2[czp + cxp*MAXRES]);

        float omx = 1.0f - fx, omy = 1.0f - fy, omz = 1.0f - fz;

        // plane 0: dims (x=d0, y=d1)
        float wa0 = omx*omy, wa1 = fx*omy, wa2 = omx*fy, wa3 = fx*fy;
        float p0x = ((wa0*a00.x + wa1*a10.x) + wa2*a01.x) + wa3*a11.x;
        float p0y = ((wa0*a00.y + wa1*a10.y) + wa2*a01.y) + wa3*a11.y;

        // plane 1: dims (y=d0, z=d1)
        float wb0 = omy*omz, wb1 = fy*omz, wb2 = omy*fz, wb3 = fy*fz;
        float p1x = ((wb0*b00.x + wb1*b10.x) + wb2*b01.x) + wb3*b11.x;
        float p1y = ((wb0*b00.y + wb1*b10.y) + wb2*b01.y) + wb3*b11.y;

        // plane 2: dims (z=d0, x=d1)
        float wc0 = omz*omx, wc1 = fz*omx, wc2 = omz*fx, wc3 = fz*fx;
        float p2x = ((wc0*c00.x + wc1*c10.x) + wc2*c01.x) + wc3*c11.x;
        float p2y = ((wc0*c00.y + wc1*c10.y) + wc2*c01.y) + wc3*c11.y;

        r[l]          = (p0x*p1x)*p2x;   // out[b, 0*16 + l]
        r[LEVELS + l] = (p0y*p1y)*p2y;   // out[b, 1*16 + l]
    }

    // each thread owns exactly one 128B output line -> 8x STG.128
    float4* o4 = (float4*)(out + (size_t)b * (2*LEVELS));
#pragma unroll
    for (int i = 0; i < 8; i++) {
        o4[i] = make_float4(r[4*i+0], r[4*i+1], r[4*i+2], r[4*i+3]);
    }
}

extern "C" void kernel_launch(void* const* d_in, const int* in_sizes, int n_in,
                              void* d_out, int out_size) {
    const float* positions = (const float*)d_in[0];
    const float* table     = (const float*)d_in[1];
    float* out             = (float*)d_out;
    int B = in_sizes[0] / 3;

    // Same double-precision sequence as the Python reference (same libm).
    LP lp;
    double logb = log(2048.0 / 16.0) / 15.0;
    for (int l = 0; l < LEVELS; l++) {
        double scale = 16.0 * exp((double)l * logb) - 1.0;
        int res = (int)ceil(scale) + 1;
        lp.resm1[l] = (float)(res - 1);
        lp.fres[l]  = (float)res;
    }

    int threads = 256;
    int blocks  = (B + threads - 1) / threads;
    triplane_kernel<<<blocks, threads>>>(positions, table, out, B, lp);
}

// round 3
// speedup vs baseline: 1.9091x; 1.9091x over previous
#include <cuda_runtime.h>
#include <math.h>

#define LEVELS 16
#define MAXRES 2048
#define BMAX   (1 << 20)
#define NB     (1 << 18)          // 18-bit Morton bins (6 bits/axis)
#define SCAN_BLK 1024
#define NBLK   (NB / SCAN_BLK)    // 256

struct LP { float resm1[LEVELS]; float fres[LEVELS]; };

// ---------------- scratch (static device globals; no allocations) -----------
__device__ unsigned int g_hist[NB];
__device__ unsigned int g_bsum[NBLK];
__device__ unsigned int g_key[BMAX];
__device__ float4       g_spos[BMAX];

// ---------------- helpers ----------------------------------------------------
__device__ __forceinline__ int quantize(float c, float fres) {
    return (int)__fmul_rn(__fdiv_rn(c, fres), 2047.0f);
}

__device__ __forceinline__ unsigned int expand3(unsigned int v) {
    v = (v | (v << 16)) & 0x030000FFu;
    v = (v | (v <<  8)) & 0x0300F00Fu;
    v = (v | (v <<  4)) & 0x030C30C3u;
    v = (v | (v <<  2)) & 0x09249249u;
    return v;
}

__device__ __forceinline__ unsigned int morton_key(float x, float y, float z) {
    int ix = (int)(x * 64.0f), iy = (int)(y * 64.0f), iz = (int)(z * 64.0f);
    unsigned int kx = (unsigned int)max(0, min(63, ix));
    unsigned int ky = (unsigned int)max(0, min(63, iy));
    unsigned int kz = (unsigned int)max(0, min(63, iz));
    return expand3(kx) | (expand3(ky) << 1) | (expand3(kz) << 2);
}

// ---------------- sort pipeline ----------------------------------------------
__global__ void zero_hist_kernel() {
    int i = blockIdx.x * blockDim.x + threadIdx.x;
    if (i < NB) g_hist[i] = 0u;
}

__global__ void hist_kernel(const float* __restrict__ positions, int B) {
    int i = blockIdx.x * blockDim.x + threadIdx.x;
    if (i >= B) return;
    float x = positions[3*i+0], y = positions[3*i+1], z = positions[3*i+2];
    unsigned int k = morton_key(x, y, z);
    g_key[i] = k;
    atomicAdd(&g_hist[k], 1u);
}

__global__ void scanA_kernel() {
    __shared__ unsigned int s[SCAN_BLK];
    int tid = threadIdx.x;
    int gid = blockIdx.x * SCAN_BLK + tid;
    unsigned int v = g_hist[gid];
    s[tid] = v;
    __syncthreads();
    for (int off = 1; off < SCAN_BLK; off <<= 1) {
        unsigned int t = (tid >= off) ? s[tid - off] : 0u;
        __syncthreads();
        s[tid] += t;
        __syncthreads();
    }
    g_hist[gid] = s[tid] - v;                 // exclusive within block
    if (tid == SCAN_BLK - 1) g_bsum[blockIdx.x] = s[tid];
}

__global__ void scanB_kernel() {
    __shared__ unsigned int s[NBLK];
    int tid = threadIdx.x;
    unsigned int v = g_bsum[tid];
    s[tid] = v;
    __syncthreads();
    for (int off = 1; off < NBLK; off <<= 1) {
        unsigned int t = (tid >= off) ? s[tid - off] : 0u;
        __syncthreads();
        s[tid] += t;
        __syncthreads();
    }
    g_bsum[tid] = s[tid] - v;                 // exclusive block sums
}

__global__ void scanC_kernel() {
    int i = blockIdx.x * blockDim.x + threadIdx.x;
    if (i < NB) g_hist[i] += g_bsum[i / SCAN_BLK];
}

__global__ void scatter_kernel(const float* __restrict__ positions, int B) {
    int i = blockIdx.x * blockDim.x + threadIdx.x;
    if (i >= B) return;
    float x = positions[3*i+0], y = positions[3*i+1], z = positions[3*i+2];
    unsigned int k = g_key[i];
    unsigned int dst = atomicAdd(&g_hist[k], 1u);
    g_spos[dst] = make_float4(x, y, z, __int_as_float(i));
}

// ---------------- main encoder -----------------------------------------------
template <bool SORTED>
__global__ void __launch_bounds__(256) triplane_kernel(
    const float* __restrict__ positions,
    const float* __restrict__ table,
    float* __restrict__ out, int B, LP lp)
{
    int i = blockIdx.x * blockDim.x + threadIdx.x;
    if (i >= B) return;

    float px, py, pz;
    int b;
    if (SORTED) {
        float4 p = g_spos[i];
        px = p.x; py = p.y; pz = p.z;
        b = __float_as_int(p.w);
    } else {
        b = i;
        px = positions[3*b+0];
        py = positions[3*b+1];
        pz = positions[3*b+2];
    }

    const float2* t0 = (const float2*)table;          // plane 0: (x,y)
    const float2* t1 = t0 + MAXRES*MAXRES;            // plane 1: (y,z)
    const float2* t2 = t1 + MAXRES*MAXRES;            // plane 2: (z,x)

    float r[2*LEVELS];

#pragma unroll
    for (int l = 0; l < LEVELS; l++) {
        float resm1 = lp.resm1[l];
        float fres  = lp.fres[l];

        // pos = p*(res-1) + 0.5, no FMA contraction (match reference)
        float posx = __fadd_rn(__fmul_rn(px, resm1), 0.5f);
        float posy = __fadd_rn(__fmul_rn(py, resm1), 0.5f);
        float posz = __fadd_rn(__fmul_rn(pz, resm1), 0.5f);
        float gx = floorf(posx), gy = floorf(posy), gz = floorf(posz);
        float fx = posx - gx, fy = posy - gy, fz = posz - gz;

        int cxm = quantize(gx, fres), cxp = quantize(gx + 1.0f, fres);
        int cym = quantize(gy, fres), cyp = quantize(gy + 1.0f, fres);
        int czm = quantize(gz, fres), czp = quantize(gz + 1.0f, fres);

        float2 a00 = __ldg(&t0[cxm + cym*MAXRES]);
        float2 a10 = __ldg(&t0[cxp + cym*MAXRES]);
        float2 a01 = __ldg(&t0[cxm + cyp*MAXRES]);
        float2 a11 = __ldg(&t0[cxp + cyp*MAXRES]);

        float2 b00 = __ldg(&t1[cym + czm*MAXRES]);
        float2 b10 = __ldg(&t1[cyp + czm*MAXRES]);
        float2 b01 = __ldg(&t1[cym + czp*MAXRES]);
        float2 b11 = __ldg(&t1[cyp + czp*MAXRES]);

        float2 c00 = __ldg(&t2[czm + cxm*MAXRES]);
        float2 c10 = __ldg(&t2[czp + cxm*MAXRES]);
        float2 c01 = __ldg(&t2[czm + cxp*MAXRES]);
        float2 c11 = __ldg(&t2[czp + cxp*MAXRES]);

        float omx = 1.0f - fx, omy = 1.0f - fy, omz = 1.0f - fz;

        float wa0 = omx*omy, wa1 = fx*omy, wa2 = omx*fy, wa3 = fx*fy;
        float p0x = ((wa0*a00.x + wa1*a10.x) + wa2*a01.x) + wa3*a11.x;
        float p0y = ((wa0*a00.y + wa1*a10.y) + wa2*a01.y) + wa3*a11.y;

        float wb0 = omy*omz, wb1 = fy*omz, wb2 = omy*fz, wb3 = fy*fz;
        float p1x = ((wb0*b00.x + wb1*b10.x) + wb2*b01.x) + wb3*b11.x;
        float p1y = ((wb0*b00.y + wb1*b10.y) + wb2*b01.y) + wb3*b11.y;

        float wc0 = omz*omx, wc1 = fz*omx, wc2 = omz*fx, wc3 = fz*fx;
        float p2x = ((wc0*c00.x + wc1*c10.x) + wc2*c01.x) + wc3*c11.x;
        float p2y = ((wc0*c00.y + wc1*c10.y) + wc2*c01.y) + wc3*c11.y;

        r[l]          = (p0x*p1x)*p2x;
        r[LEVELS + l] = (p0y*p1y)*p2y;
    }

    float4* o4 = (float4*)(out + (size_t)b * (2*LEVELS));
#pragma unroll
    for (int k = 0; k < 8; k++)
        o4[k] = make_float4(r[4*k+0], r[4*k+1], r[4*k+2], r[4*k+3]);
}

// ---------------- launch -----------------------------------------------------
extern "C" void kernel_launch(void* const* d_in, const int* in_sizes, int n_in,
                              void* d_out, int out_size) {
    const float* positions = (const float*)d_in[0];
    const float* table     = (const float*)d_in[1];
    float* out             = (float*)d_out;
    int B = in_sizes[0] / 3;

    LP lp;
    double logb = log(2048.0 / 16.0) / 15.0;
    for (int l = 0; l < LEVELS; l++) {
        double scale = 16.0 * exp((double)l * logb) - 1.0;
        int res = (int)ceil(scale) + 1;
        lp.resm1[l] = (float)(res - 1);
        lp.fres[l]  = (float)res;
    }

    int threads = 256;
    int blocks  = (B + threads - 1) / threads;

    if (B <= BMAX) {
        zero_hist_kernel<<<NB / 256, 256>>>();
        hist_kernel<<<blocks, threads>>>(positions, B);
        scanA_kernel<<<NBLK, SCAN_BLK>>>();
        scanB_kernel<<<1, NBLK>>>();
        scanC_kernel<<<NB / 256, 256>>>();
        scatter_kernel<<<blocks, threads>>>(positions, B);
        triplane_kernel<true><<<blocks, threads>>>(positions, table, out, B, lp);
    } else {
        triplane_kernel<false><<<blocks, threads>>>(positions, table, out, B, lp);
    }
}